// round 11
// baseline (speedup 1.0000x reference)
#include <cuda_runtime.h>
#include <cstdint>

// FlowDE R11: R10 (u64 {h,l} interleaved split planes, LDS.64 fragment loads)
// with the PV leading-dim bug fixed: PV tiles have 64 pairs per row, so
// LDP2 = 68 (R10 wrongly reused the QK value 36 -> SMEM overrun).

#define Nn 4096
#define Mm 4096
#define Dd 64
#define Tt 8
#define Hh 0.125f
#define S0c 0.001f
#define MBLK 32
#define LDQ 36   // u64 leading dim, QK pair tiles [128][36] (32 k-pairs + pad)
#define LDP2 68  // u64 leading dim, PV pair tiles (64 m-pairs + pad)

typedef unsigned long long u64;
typedef uint32_t u32;

__device__ __forceinline__ u64 packf(float lo, float hi) {
    u64 r; asm("mov.b64 %0, {%1, %2};" : "=l"(r) : "f"(lo), "f"(hi)); return r;
}
__device__ __forceinline__ u64 packu(u32 lo, u32 hi) {
    u64 r; asm("mov.b64 %0, {%1, %2};" : "=l"(r) : "r"(lo), "r"(hi)); return r;
}
__device__ __forceinline__ void unpku(u32& lo, u32& hi, u64 v) {
    asm("mov.b64 {%0, %1}, %2;" : "=r"(lo), "=r"(hi) : "l"(v));
}
__device__ __forceinline__ u32 to_tf32(float v) {
    u32 r; asm("cvt.rna.tf32.f32 %0, %1;" : "=r"(r) : "f"(v)); return r;
}
__device__ __forceinline__ void mma_tf32(float* d, const u32* a, const u32* b) {
    asm("mma.sync.aligned.m16n8k8.row.col.f32.tf32.tf32.f32 "
        "{%0,%1,%2,%3}, {%4,%5,%6,%7}, {%8,%9}, {%0,%1,%2,%3};"
        : "+f"(d[0]), "+f"(d[1]), "+f"(d[2]), "+f"(d[3])
        : "r"(a[0]), "r"(a[1]), "r"(a[2]), "r"(a[3]), "r"(b[0]), "r"(b[1]));
}
__device__ __forceinline__ void mma_bf16(float* d, const u32* a, u32 b0, u32 b1) {
    asm("mma.sync.aligned.m16n8k16.row.col.f32.bf16.bf16.f32 "
        "{%0,%1,%2,%3}, {%4,%5,%6,%7}, {%8,%9}, {%0,%1,%2,%3};"
        : "+f"(d[0]), "+f"(d[1]), "+f"(d[2]), "+f"(d[3])
        : "r"(a[0]), "r"(a[1]), "r"(a[2]), "r"(a[3]), "r"(b0), "r"(b1));
}
__device__ __forceinline__ u32 bf16pair(float v0, float v1) {
    u32 r; asm("cvt.rn.bf16x2.f32 %0, %1, %2;" : "=r"(r) : "f"(v1), "f"(v0));
    return r;
}
__device__ __forceinline__ float bf16lo_f(u32 p) { return __uint_as_float(p << 16); }
__device__ __forceinline__ float bf16hi_f(u32 p) {
    return __uint_as_float(p & 0xffff0000u);
}

// ---------------- globals -----------------------------------------------------
__device__ float g_xt[Nn * Dd];
__device__ float g_xeff[Nn * Dd];
__device__ float g_G1[Nn * Dd];
__device__ float g_x0sq[Mm];
__device__ float g_pmax[MBLK * Nn];
__device__ float g_psum[MBLK * Nn];
__device__ float g_qpart[(size_t)MBLK * Nn * Dd];
__device__ float g_xh32[Nn * Dd], g_xl32[Nn * Dd];     // tf32 split (QK A)
__device__ float g_x0h32[Mm * Dd], g_x0l32[Mm * Dd];   // tf32 split (QK B)
__device__ u64 g_x0b[Dd * (Mm / 2)];   // x0^T bf16 {h-pair, l-pair} [d][m/2]

__device__ __forceinline__ void split_tf32(float v, int idx, float* h, float* l) {
    u32 hb = to_tf32(v);
    float hf = __uint_as_float(hb);
    u32 lb = to_tf32(v - hf);
    h[idx] = hf;
    l[idx] = __uint_as_float(lb);
}

// ---------------------------------------------------------------------------
__global__ void k_init(const float* __restrict__ z, const float* __restrict__ x0) {
    int idx = blockIdx.x * blockDim.x + threadIdx.x;
    if (idx < Nn * Dd) {
        float v = z[idx];
        g_xt[idx] = v;
        g_xeff[idx] = v;
        split_tf32(v, idx, g_xh32, g_xl32);
        split_tf32(x0[idx], idx, g_x0h32, g_x0l32);
    }
    if (idx < Mm) {
        const float4* r = reinterpret_cast<const float4*>(x0 + idx * Dd);
        float s = 0.f;
#pragma unroll
        for (int i = 0; i < Dd / 4; i++) {
            float4 v = r[i];
            s += v.x * v.x + v.y * v.y + v.z * v.z + v.w * v.w;
        }
        g_x0sq[idx] = s;
    }
    if (idx < Dd * (Mm / 2)) {
        int d = idx >> 11;
        int mp = idx & 2047;
        float v0 = x0[(2 * mp) * Dd + d];
        float v1 = x0[(2 * mp + 1) * Dd + d];
        u32 ph = bf16pair(v0, v1);
        u32 pl = bf16pair(v0 - bf16lo_f(ph), v1 - bf16hi_f(ph));
        g_x0b[idx] = packu(ph, pl);
    }
}

// ---------------------------------------------------------------------------
// SMEM map (dynamic, 112640 B):
//  [0,512)         x0sq
//  [1024,2048)     pm [128][2]
//  [2048,3072)     ps [128][2]
//  [4096,77824)    QK pair tiles Apair[128][LDQ]u64 | Bpair[128][LDQ]u64 (73728)
//                  -> post-QK aliased by Ppair[128][LDP2]u64 (69632) @4096
//  [77824,112640)  X0pair [64][LDP2]u64 (34816)
// ---------------------------------------------------------------------------
extern __shared__ char dsm[];

__global__ __launch_bounds__(256, 2) void k_fused(float scale, float c2) {
    const int tid = threadIdx.x;
    const int m0 = blockIdx.x * 128;
    const int n0 = blockIdx.y * 128;

    float* x0sq_s = reinterpret_cast<float*>(dsm);
    float* pm = reinterpret_cast<float*>(dsm + 1024);
    float* ps = reinterpret_cast<float*>(dsm + 2048);
    u64* Apair = reinterpret_cast<u64*>(dsm + 4096);
    u64* Bpair = Apair + 128 * LDQ;
    u64* Ppair = reinterpret_cast<u64*>(dsm + 4096);     // alias post-QK
    u64* X0pair = reinterpret_cast<u64*>(dsm + 77824);

    const int wid = tid >> 5;
    const int lane = tid & 31;
    const int wr = wid >> 1;
    const int wc = wid & 1;
    const int g = lane >> 2;
    const int tg = lane & 3;

    if (tid < 128) x0sq_s[tid] = g_x0sq[m0 + tid];

    // load x0^T bf16 pair tile: 64 d-rows x 64 m-pairs (u64 each)
#pragma unroll
    for (int it = 0; it < 8; it++) {
        int lin = tid + 256 * it;            // 0..2047 ulonglong2 slots
        int d = lin >> 5, mp2 = lin & 31;
        *reinterpret_cast<ulonglong2*>(&X0pair[d * LDP2 + 2 * mp2]) =
            *reinterpret_cast<const ulonglong2*>(
                &g_x0b[d * (Mm / 2) + m0 / 2 + 2 * mp2]);
    }

    float c[2][8][4];
#pragma unroll
    for (int rf = 0; rf < 2; rf++)
#pragma unroll
        for (int cm = 0; cm < 8; cm++)
#pragma unroll
            for (int e = 0; e < 4; e++) c[rf][cm][e] = 0.f;

    // ================= QK (tf32 3-product) =================
    for (int kk = 0; kk < 2; kk++) {
        __syncthreads();
        // A tile: rows n0.., planes g_xh32/g_xl32 -> u64 pairs
#pragma unroll
        for (int it = 0; it < 4; it++) {
            int idx = tid + 256 * it;        // 0..1023
            int row = idx >> 3, q = idx & 7; // 8 quad-col groups
            float4 vh = *reinterpret_cast<const float4*>(
                &g_xh32[(n0 + row) * Dd + kk * 32 + 4 * q]);
            float4 vl = *reinterpret_cast<const float4*>(
                &g_xl32[(n0 + row) * Dd + kk * 32 + 4 * q]);
            u64* dst = &Apair[row * LDQ + 4 * q];
            *reinterpret_cast<ulonglong2*>(dst) =
                make_ulonglong2(packf(vh.x, vl.x), packf(vh.y, vl.y));
            *reinterpret_cast<ulonglong2*>(dst + 2) =
                make_ulonglong2(packf(vh.z, vl.z), packf(vh.w, vl.w));
        }
        // B tile: rows m0..
#pragma unroll
        for (int it = 0; it < 4; it++) {
            int idx = tid + 256 * it;
            int row = idx >> 3, q = idx & 7;
            float4 vh = *reinterpret_cast<const float4*>(
                &g_x0h32[(m0 + row) * Dd + kk * 32 + 4 * q]);
            float4 vl = *reinterpret_cast<const float4*>(
                &g_x0l32[(m0 + row) * Dd + kk * 32 + 4 * q]);
            u64* dst = &Bpair[row * LDQ + 4 * q];
            *reinterpret_cast<ulonglong2*>(dst) =
                make_ulonglong2(packf(vh.x, vl.x), packf(vh.y, vl.y));
            *reinterpret_cast<ulonglong2*>(dst + 2) =
                make_ulonglong2(packf(vh.z, vl.z), packf(vh.w, vl.w));
        }
        __syncthreads();

#pragma unroll
        for (int ks = 0; ks < 4; ks++) {
            int co = 8 * ks + tg;
            u32 ah[2][4], al[2][4];
#pragma unroll
            for (int rf = 0; rf < 2; rf++) {
                int rb = 32 * wr + 16 * rf;
                unpku(ah[rf][0], al[rf][0], Apair[(rb + g) * LDQ + co]);
                unpku(ah[rf][1], al[rf][1], Apair[(rb + g + 8) * LDQ + co]);
                unpku(ah[rf][2], al[rf][2], Apair[(rb + g) * LDQ + co + 4]);
                unpku(ah[rf][3], al[rf][3], Apair[(rb + g + 8) * LDQ + co + 4]);
            }
#pragma unroll
            for (int cm = 0; cm < 8; cm++) {
                int cb = 64 * wc + 8 * cm;
                u32 bh[2], bl[2];
                unpku(bh[0], bl[0], Bpair[(cb + g) * LDQ + co]);
                unpku(bh[1], bl[1], Bpair[(cb + g) * LDQ + co + 4]);
#pragma unroll
                for (int rf = 0; rf < 2; rf++) {
                    mma_tf32(c[rf][cm], ah[rf], bh);
                    mma_tf32(c[rf][cm], ah[rf], bl);
                    mma_tf32(c[rf][cm], al[rf], bh);
                }
            }
        }
    }
    __syncthreads();   // QK tile reads done -> Ppair alias writable later

    // ---- pass 1: bias in place, per-row(half) max ----
#pragma unroll
    for (int rf = 0; rf < 2; rf++) {
#pragma unroll
        for (int rh = 0; rh < 2; rh++) {
            float mx = -1e30f;
#pragma unroll
            for (int cm = 0; cm < 8; cm++) {
                int col = 64 * wc + 8 * cm + 2 * tg;
                float l0 = fmaf(scale, c[rf][cm][2 * rh], -c2 * x0sq_s[col]);
                float l1 = fmaf(scale, c[rf][cm][2 * rh + 1], -c2 * x0sq_s[col + 1]);
                c[rf][cm][2 * rh] = l0;
                c[rf][cm][2 * rh + 1] = l1;
                mx = fmaxf(mx, fmaxf(l0, l1));
            }
#pragma unroll
            for (int o = 1; o <= 2; o <<= 1)
                mx = fmaxf(mx, __shfl_xor_sync(0xffffffffu, mx, o));
            if (tg == 0) pm[(32 * wr + 16 * rf + 8 * rh + g) * 2 + wc] = mx;
        }
    }
    __syncthreads();

    // ---- pass 2: exp, bf16x2 split, pair-pack into Ppair; row sums ----
#pragma unroll
    for (int rf = 0; rf < 2; rf++) {
#pragma unroll
        for (int rh = 0; rh < 2; rh++) {
            int row = 32 * wr + 16 * rf + 8 * rh + g;
            float M = fmaxf(pm[row * 2], pm[row * 2 + 1]);
            float sm = 0.f;
#pragma unroll
            for (int cm = 0; cm < 8; cm++) {
                float e0 = __expf(c[rf][cm][2 * rh] - M);
                float e1 = __expf(c[rf][cm][2 * rh + 1] - M);
                u32 ph = bf16pair(e0, e1);
                u32 pl = bf16pair(e0 - bf16lo_f(ph), e1 - bf16hi_f(ph));
                int cp = 32 * wc + 4 * cm + tg;
                Ppair[row * LDP2 + cp] = packu(ph, pl);
                sm += e0 + e1;
            }
#pragma unroll
            for (int o = 1; o <= 2; o <<= 1)
                sm += __shfl_xor_sync(0xffffffffu, sm, o);
            if (tg == 0) ps[row * 2 + wc] = sm;
        }
    }
    __syncthreads();

    if (tid < 128) {
        g_pmax[blockIdx.x * Nn + n0 + tid] = fmaxf(pm[tid * 2], pm[tid * 2 + 1]);
        g_psum[blockIdx.x * Nn + n0 + tid] = ps[tid * 2] + ps[tid * 2 + 1];
    }

    // ================= PV (bf16 3-product) =================
    const int wr2 = wid >> 1;
    const int wc2 = wid & 1;
    float cc[2][4][4];
#pragma unroll
    for (int rf = 0; rf < 2; rf++)
#pragma unroll
        for (int cm = 0; cm < 4; cm++)
#pragma unroll
            for (int e = 0; e < 4; e++) cc[rf][cm][e] = 0.f;

#pragma unroll
    for (int ks = 0; ks < 8; ks++) {
        int kp = 8 * ks + tg;
        u32 pah[2][4], pal[2][4];
#pragma unroll
        for (int rf = 0; rf < 2; rf++) {
            int rb = 32 * wr2 + 16 * rf;
            unpku(pah[rf][0], pal[rf][0], Ppair[(rb + g) * LDP2 + kp]);
            unpku(pah[rf][1], pal[rf][1], Ppair[(rb + g + 8) * LDP2 + kp]);
            unpku(pah[rf][2], pal[rf][2], Ppair[(rb + g) * LDP2 + kp + 4]);
            unpku(pah[rf][3], pal[rf][3], Ppair[(rb + g + 8) * LDP2 + kp + 4]);
        }
#pragma unroll
        for (int cm = 0; cm < 4; cm++) {
            int cb = 32 * wc2 + 8 * cm;
            u32 bh0, bl0, bh1, bl1;
            unpku(bh0, bl0, X0pair[(cb + g) * LDP2 + kp]);
            unpku(bh1, bl1, X0pair[(cb + g) * LDP2 + kp + 4]);
#pragma unroll
            for (int rf = 0; rf < 2; rf++) {
                mma_bf16(cc[rf][cm], pah[rf], bh0, bh1);
                mma_bf16(cc[rf][cm], pah[rf], bl0, bl1);
                mma_bf16(cc[rf][cm], pal[rf], bh0, bh1);
            }
        }
    }

    // write qpart slice
#pragma unroll
    for (int rf = 0; rf < 2; rf++) {
#pragma unroll
        for (int cm = 0; cm < 4; cm++) {
            int row0 = 32 * wr2 + 16 * rf + g;
            int col = 32 * wc2 + 8 * cm + 2 * tg;
            size_t base = (size_t)blockIdx.x * Nn * Dd;
            *reinterpret_cast<float2*>(&g_qpart[base + (size_t)(n0 + row0) * Dd + col]) =
                make_float2(cc[rf][cm][0], cc[rf][cm][1]);
            *reinterpret_cast<float2*>(
                &g_qpart[base + (size_t)(n0 + row0 + 8) * Dd + col]) =
                make_float2(cc[rf][cm][2], cc[rf][cm][3]);
        }
    }
}

// ---------------------------------------------------------------------------
__global__ void k_update(float sigmat, int first, int last, float* __restrict__ out) {
    int i4 = blockIdx.x * blockDim.x + threadIdx.x;
    if (i4 >= Nn * Dd / 4) return;
    int n = i4 >> 4;

    float mx = -1e30f;
#pragma unroll
    for (int s = 0; s < MBLK; s++) mx = fmaxf(mx, g_pmax[s * Nn + n]);
    float rsum = 0.f;
    float4 q = make_float4(0.f, 0.f, 0.f, 0.f);
#pragma unroll
    for (int s = 0; s < MBLK; s++) {
        float ef = __expf(g_pmax[s * Nn + n] - mx);
        rsum = fmaf(g_psum[s * Nn + n], ef, rsum);
        float4 v = *reinterpret_cast<const float4*>(
            &g_qpart[(size_t)s * Nn * Dd + 4 * i4]);
        q.x = fmaf(v.x, ef, q.x);
        q.y = fmaf(v.y, ef, q.y);
        q.z = fmaf(v.z, ef, q.z);
        q.w = fmaf(v.w, ef, q.w);
    }
    float inv = 1.f / rsum;
    float4 xe = *reinterpret_cast<const float4*>(&g_xeff[4 * i4]);
    float4 xt = *reinterpret_cast<const float4*>(&g_xt[4 * i4]);
    float4 G1o = make_float4(0.f, 0.f, 0.f, 0.f);
    if (!first) G1o = *reinterpret_cast<const float4*>(&g_G1[4 * i4]);
    float4 G, xe2, xh, xl;
    float* Gp = &G.x; float* qp = &q.x; float* xep = &xe.x;
    float* xtp = &xt.x; float* xe2p = &xe2.x; float* xhp = &xh.x; float* xlp = &xl.x;
    float* G1p = &G1o.x;
#pragma unroll
    for (int e = 0; e < 4; e++) {
        float Gv = ((1.f - S0c) * xep[e] - qp[e] * inv) / sigmat;
        Gp[e] = Gv;
        if (!first) xtp[e] = xtp[e] - (G1p[e] + Gv) * (Hh * 0.5f);
        float x2 = xtp[e] - Hh * Gv;
        xe2p[e] = x2;
        u32 hb = to_tf32(x2);
        float hf = __uint_as_float(hb);
        xhp[e] = hf;
        xlp[e] = __uint_as_float(to_tf32(x2 - hf));
    }
    if (!first) *reinterpret_cast<float4*>(&g_xt[4 * i4]) = xt;
    *reinterpret_cast<float4*>(&g_G1[4 * i4]) = G;
    *reinterpret_cast<float4*>(&g_xeff[4 * i4]) = xe2;
    *reinterpret_cast<float4*>(&g_xh32[4 * i4]) = xh;
    *reinterpret_cast<float4*>(&g_xl32[4 * i4]) = xl;
    if (last) *reinterpret_cast<float4*>(&out[4 * i4]) = xt;
}

// ---------------------------------------------------------------------------
extern "C" void kernel_launch(void* const* d_in, const int* in_sizes, int n_in,
                              void* d_out, int out_size) {
    const float* z = (const float*)d_in[0];
    const float* x0 = (const float*)d_in[1];

    const int SMEM_F = 112640;
    cudaFuncSetAttribute(k_fused, cudaFuncAttributeMaxDynamicSharedMemorySize,
                         SMEM_F);

    k_init<<<(Nn * Dd + 255) / 256, 256>>>(z, x0);

    for (int e = 0; e < Tt; e++) {
        float t = (e == 0) ? 1.0f : (float)(Tt - e) / (float)Tt;
        float alphat = 1.0f - t;
        float sigmat = S0c + (1.0f - S0c) * t;
        float inv2s2 = 1.0f / (sigmat * sigmat);
        float scale = alphat * inv2s2;
        float c2 = 0.5f * alphat * alphat * inv2s2;

        k_fused<<<dim3(MBLK, 32), 256, SMEM_F>>>(scale, c2);
        k_update<<<(Nn * Dd / 4) / 256, 256>>>(sigmat, e == 0, e == Tt - 1,
                                               (float*)d_out);
    }
}

// round 12
// speedup vs baseline: 1.2466x; 1.2466x over previous
#include <cuda_runtime.h>
#include <cstdint>

// FlowDE R12: register-resident P (FA2 trick). QK tf32x3 mma -> logits stay in
// C fragments -> softmax+bf16x2 split in registers -> PV bf16x3 mma consumes
// the packed pairs directly as A-operands (QK C layout == PV A layout when
// P's m-cols are the k-dim). No P~ SMEM round trip. Cross-wc partial-k
// reduction through two f32 buffers aliasing the dead QK staging tiles.

#define Nn 4096
#define Mm 4096
#define Dd 64
#define Tt 8
#define Hh 0.125f
#define S0c 0.001f
#define MBLK 32
#define LDT 36   // u32 leading dim, QK staging planes
#define LDP 68   // u32 leading dim, X0 pair planes [64][68]
#define LDB 68   // f32 leading dim, PV reduce buffers [128][68]

typedef unsigned long long u64;
typedef uint32_t u32;

__device__ __forceinline__ u32 to_tf32(float v) {
    u32 r; asm("cvt.rna.tf32.f32 %0, %1;" : "=r"(r) : "f"(v)); return r;
}
__device__ __forceinline__ void mma_tf32(float* d, const u32* a, const u32* b) {
    asm("mma.sync.aligned.m16n8k8.row.col.f32.tf32.tf32.f32 "
        "{%0,%1,%2,%3}, {%4,%5,%6,%7}, {%8,%9}, {%0,%1,%2,%3};"
        : "+f"(d[0]), "+f"(d[1]), "+f"(d[2]), "+f"(d[3])
        : "r"(a[0]), "r"(a[1]), "r"(a[2]), "r"(a[3]), "r"(b[0]), "r"(b[1]));
}
__device__ __forceinline__ void mma_bf16(float* d, const u32* a, u32 b0, u32 b1) {
    asm("mma.sync.aligned.m16n8k16.row.col.f32.bf16.bf16.f32 "
        "{%0,%1,%2,%3}, {%4,%5,%6,%7}, {%8,%9}, {%0,%1,%2,%3};"
        : "+f"(d[0]), "+f"(d[1]), "+f"(d[2]), "+f"(d[3])
        : "r"(a[0]), "r"(a[1]), "r"(a[2]), "r"(a[3]), "r"(b0), "r"(b1));
}
__device__ __forceinline__ u32 bf16pair(float v0, float v1) {
    u32 r; asm("cvt.rn.bf16x2.f32 %0, %1, %2;" : "=r"(r) : "f"(v1), "f"(v0));
    return r;
}
__device__ __forceinline__ float bf16lo_f(u32 p) { return __uint_as_float(p << 16); }
__device__ __forceinline__ float bf16hi_f(u32 p) {
    return __uint_as_float(p & 0xffff0000u);
}

// ---------------- globals -----------------------------------------------------
__device__ float g_xt[Nn * Dd];
__device__ float g_xeff[Nn * Dd];
__device__ float g_G1[Nn * Dd];
__device__ float g_x0sq[Mm];
__device__ float g_pmax[MBLK * Nn];
__device__ float g_psum[MBLK * Nn];
__device__ float g_qpart[(size_t)MBLK * Nn * Dd];
__device__ float g_xh32[Nn * Dd], g_xl32[Nn * Dd];     // tf32 split (QK A)
__device__ float g_x0h32[Mm * Dd], g_x0l32[Mm * Dd];   // tf32 split (QK B)
__device__ u32 g_x0bh[Dd * (Mm / 2)];  // x0^T bf16-high pairs [d][m/2]
__device__ u32 g_x0bl[Dd * (Mm / 2)];  // x0^T bf16-low  pairs [d][m/2]

__device__ __forceinline__ void split_tf32(float v, int idx, float* h, float* l) {
    u32 hb = to_tf32(v);
    float hf = __uint_as_float(hb);
    u32 lb = to_tf32(v - hf);
    h[idx] = hf;
    l[idx] = __uint_as_float(lb);
}

// ---------------------------------------------------------------------------
__global__ void k_init(const float* __restrict__ z, const float* __restrict__ x0) {
    int idx = blockIdx.x * blockDim.x + threadIdx.x;
    if (idx < Nn * Dd) {
        float v = z[idx];
        g_xt[idx] = v;
        g_xeff[idx] = v;
        split_tf32(v, idx, g_xh32, g_xl32);
        split_tf32(x0[idx], idx, g_x0h32, g_x0l32);
    }
    if (idx < Mm) {
        const float4* r = reinterpret_cast<const float4*>(x0 + idx * Dd);
        float s = 0.f;
#pragma unroll
        for (int i = 0; i < Dd / 4; i++) {
            float4 v = r[i];
            s += v.x * v.x + v.y * v.y + v.z * v.z + v.w * v.w;
        }
        g_x0sq[idx] = s;
    }
    if (idx < Dd * (Mm / 2)) {
        int d = idx >> 11;
        int mp = idx & 2047;
        float v0 = x0[(2 * mp) * Dd + d];
        float v1 = x0[(2 * mp + 1) * Dd + d];
        u32 ph = bf16pair(v0, v1);
        g_x0bh[idx] = ph;
        g_x0bl[idx] = bf16pair(v0 - bf16lo_f(ph), v1 - bf16hi_f(ph));
    }
}

// ---------------------------------------------------------------------------
// SMEM map (dynamic, 112640 B):
//  [0,512)         x0sq
//  [1024,2048)     pm [128][2]
//  [2048,3072)     ps [128][2]
//  [4096,77824)    QK tf32 staging Ah|Al|Bh|Bl  (73728)
//                  -> post-QK aliased by buf1[128][LDB]f32 @4096 (34816)
//                                        buf2[128][LDB]f32 @38912 (34816)
//  [77824,95232)   X0bh [64][LDP]u32
//  [95232,112640)  X0bl [64][LDP]u32
// ---------------------------------------------------------------------------
extern __shared__ char dsm[];

__global__ __launch_bounds__(256, 2) void k_fused(float scale, float c2) {
    const int tid = threadIdx.x;
    const int m0 = blockIdx.x * 128;
    const int n0 = blockIdx.y * 128;

    float* x0sq_s = reinterpret_cast<float*>(dsm);
    float* pm = reinterpret_cast<float*>(dsm + 1024);
    float* ps = reinterpret_cast<float*>(dsm + 2048);
    u32* tiles = reinterpret_cast<u32*>(dsm + 4096);
    u32* Ah = tiles;
    u32* Al = tiles + 128 * LDT;
    u32* Bh = tiles + 2 * 128 * LDT;
    u32* Bl = tiles + 3 * 128 * LDT;
    float* buf1 = reinterpret_cast<float*>(dsm + 4096);    // alias post-QK
    float* buf2 = reinterpret_cast<float*>(dsm + 38912);   // alias post-QK
    u32* X0bh = reinterpret_cast<u32*>(dsm + 77824);
    u32* X0bl = reinterpret_cast<u32*>(dsm + 95232);

    const int wid = tid >> 5;
    const int lane = tid & 31;
    const int wr = wid >> 1;
    const int wc = wid & 1;
    const int g = lane >> 2;
    const int tg = lane & 3;

    if (tid < 128) x0sq_s[tid] = g_x0sq[m0 + tid];

    // load x0^T bf16 pair tiles (cols m0/2 .. m0/2+63)
#pragma unroll
    for (int it = 0; it < 16; it++) {
        int lin = tid + 256 * it;            // 0..4095
        int d = lin >> 6, mp = lin & 63;
        X0bh[d * LDP + mp] = g_x0bh[d * (Mm / 2) + m0 / 2 + mp];
        X0bl[d * LDP + mp] = g_x0bl[d * (Mm / 2) + m0 / 2 + mp];
    }

    float c[2][8][4];
#pragma unroll
    for (int rf = 0; rf < 2; rf++)
#pragma unroll
        for (int cm = 0; cm < 8; cm++)
#pragma unroll
            for (int e = 0; e < 4; e++) c[rf][cm][e] = 0.f;

    const float* srcs[4] = {g_xh32 + (size_t)n0 * Dd, g_xl32 + (size_t)n0 * Dd,
                            g_x0h32 + (size_t)m0 * Dd, g_x0l32 + (size_t)m0 * Dd};

    // ================= QK (tf32 3-product) =================
    for (int kk = 0; kk < 2; kk++) {
        __syncthreads();
#pragma unroll
        for (int t = 0; t < 4; t++) {
            u32* tb = tiles + t * 128 * LDT;
            const float* src = srcs[t];
#pragma unroll
            for (int it = 0; it < 4; it++) {
                int idx = tid + 256 * it;
                int row = idx >> 3, q = idx & 7;
                float4 v = *reinterpret_cast<const float4*>(
                    &src[row * Dd + kk * 32 + 4 * q]);
                *reinterpret_cast<float4*>(&tb[row * LDT + 4 * q]) = v;
            }
        }
        __syncthreads();

#pragma unroll
        for (int ks = 0; ks < 4; ks++) {
            int co = 8 * ks + tg;
            u32 ah[2][4], al[2][4];
#pragma unroll
            for (int rf = 0; rf < 2; rf++) {
                int rb = 32 * wr + 16 * rf;
                ah[rf][0] = Ah[(rb + g) * LDT + co];
                ah[rf][1] = Ah[(rb + g + 8) * LDT + co];
                ah[rf][2] = Ah[(rb + g) * LDT + co + 4];
                ah[rf][3] = Ah[(rb + g + 8) * LDT + co + 4];
                al[rf][0] = Al[(rb + g) * LDT + co];
                al[rf][1] = Al[(rb + g + 8) * LDT + co];
                al[rf][2] = Al[(rb + g) * LDT + co + 4];
                al[rf][3] = Al[(rb + g + 8) * LDT + co + 4];
            }
#pragma unroll
            for (int cm = 0; cm < 8; cm++) {
                int cb = 64 * wc + 8 * cm;
                u32 bh[2], bl[2];
                bh[0] = Bh[(cb + g) * LDT + co];
                bh[1] = Bh[(cb + g) * LDT + co + 4];
                bl[0] = Bl[(cb + g) * LDT + co];
                bl[1] = Bl[(cb + g) * LDT + co + 4];
#pragma unroll
                for (int rf = 0; rf < 2; rf++) {
                    mma_tf32(c[rf][cm], ah[rf], bh);
                    mma_tf32(c[rf][cm], ah[rf], bl);
                    mma_tf32(c[rf][cm], al[rf], bh);
                }
            }
        }
    }
    __syncthreads();   // QK staging reads done -> buf1/buf2 alias writable later

    // ---- pass 1: bias in place, per-row(half) max ----
#pragma unroll
    for (int rf = 0; rf < 2; rf++) {
#pragma unroll
        for (int rh = 0; rh < 2; rh++) {
            float mx = -1e30f;
#pragma unroll
            for (int cm = 0; cm < 8; cm++) {
                int col = 64 * wc + 8 * cm + 2 * tg;
                float l0 = fmaf(scale, c[rf][cm][2 * rh], -c2 * x0sq_s[col]);
                float l1 = fmaf(scale, c[rf][cm][2 * rh + 1], -c2 * x0sq_s[col + 1]);
                c[rf][cm][2 * rh] = l0;
                c[rf][cm][2 * rh + 1] = l1;
                mx = fmaxf(mx, fmaxf(l0, l1));
            }
#pragma unroll
            for (int o = 1; o <= 2; o <<= 1)
                mx = fmaxf(mx, __shfl_xor_sync(0xffffffffu, mx, o));
            if (tg == 0) pm[(32 * wr + 16 * rf + 8 * rh + g) * 2 + wc] = mx;
        }
    }
    __syncthreads();

    // ---- pass 2: exp + bf16x2 split, all in registers; row sums ----
    u32 ph[2][8][2], pl[2][8][2];
#pragma unroll
    for (int rf = 0; rf < 2; rf++) {
#pragma unroll
        for (int rh = 0; rh < 2; rh++) {
            int row = 32 * wr + 16 * rf + 8 * rh + g;
            float M = fmaxf(pm[row * 2], pm[row * 2 + 1]);
            float sm = 0.f;
#pragma unroll
            for (int cm = 0; cm < 8; cm++) {
                float e0 = __expf(c[rf][cm][2 * rh] - M);
                float e1 = __expf(c[rf][cm][2 * rh + 1] - M);
                u32 hp = bf16pair(e0, e1);
                ph[rf][cm][rh] = hp;
                pl[rf][cm][rh] = bf16pair(e0 - bf16lo_f(hp), e1 - bf16hi_f(hp));
                sm += e0 + e1;
            }
#pragma unroll
            for (int o = 1; o <= 2; o <<= 1)
                sm += __shfl_xor_sync(0xffffffffu, sm, o);
            if (tg == 0) ps[row * 2 + wc] = sm;
        }
    }
    __syncthreads();

    if (tid < 128) {
        g_pmax[blockIdx.x * Nn + n0 + tid] = fmaxf(pm[tid * 2], pm[tid * 2 + 1]);
        g_psum[blockIdx.x * Nn + n0 + tid] = ps[tid * 2] + ps[tid * 2 + 1];
    }

    // ================= PV (bf16 3-product, A from registers) =================
    // Each warp covers its 64 m-cols (partial k); d in two halves of 32.
    float* mybuf = wc ? buf2 : buf1;
#pragma unroll
    for (int dh = 0; dh < 2; dh++) {
        float cc[2][4][4];
#pragma unroll
        for (int rf = 0; rf < 2; rf++)
#pragma unroll
            for (int dcm = 0; dcm < 4; dcm++)
#pragma unroll
                for (int e = 0; e < 4; e++) cc[rf][dcm][e] = 0.f;

#pragma unroll
        for (int j = 0; j < 4; j++) {
            u32 a_h[2][4], a_l[2][4];
#pragma unroll
            for (int rf = 0; rf < 2; rf++) {
                a_h[rf][0] = ph[rf][2 * j][0];
                a_h[rf][1] = ph[rf][2 * j][1];
                a_h[rf][2] = ph[rf][2 * j + 1][0];
                a_h[rf][3] = ph[rf][2 * j + 1][1];
                a_l[rf][0] = pl[rf][2 * j][0];
                a_l[rf][1] = pl[rf][2 * j][1];
                a_l[rf][2] = pl[rf][2 * j + 1][0];
                a_l[rf][3] = pl[rf][2 * j + 1][1];
            }
            int kp = 32 * wc + 8 * j + tg;     // k pair index into X0 rows
#pragma unroll
            for (int dcm = 0; dcm < 4; dcm++) {
                int dr = 32 * dh + 8 * dcm + g;
                u32 bh0 = X0bh[dr * LDP + kp];
                u32 bh1 = X0bh[dr * LDP + kp + 4];
                u32 bl0 = X0bl[dr * LDP + kp];
                u32 bl1 = X0bl[dr * LDP + kp + 4];
#pragma unroll
                for (int rf = 0; rf < 2; rf++) {
                    mma_bf16(cc[rf][dcm], a_h[rf], bh0, bh1);
                    mma_bf16(cc[rf][dcm], a_h[rf], bl0, bl1);
                    mma_bf16(cc[rf][dcm], a_l[rf], bh0, bh1);
                }
            }
        }

        // stash partials to this wc's buffer
#pragma unroll
        for (int rf = 0; rf < 2; rf++) {
#pragma unroll
            for (int dcm = 0; dcm < 4; dcm++) {
                int row = 32 * wr + 16 * rf + g;
                int col = 32 * dh + 8 * dcm + 2 * tg;
                *reinterpret_cast<float2*>(&mybuf[row * LDB + col]) =
                    make_float2(cc[rf][dcm][0], cc[rf][dcm][1]);
                *reinterpret_cast<float2*>(&mybuf[(row + 8) * LDB + col]) =
                    make_float2(cc[rf][dcm][2], cc[rf][dcm][3]);
            }
        }
    }
    __syncthreads();

    // cross-wc reduce + coalesced store of qpart slice
#pragma unroll
    for (int it = 0; it < 8; it++) {
        int lin = tid + 256 * it;            // 0..2047 float4 slots
        int row = lin >> 4, q4 = lin & 15;
        float4 v1 = *reinterpret_cast<const float4*>(&buf1[row * LDB + 4 * q4]);
        float4 v2 = *reinterpret_cast<const float4*>(&buf2[row * LDB + 4 * q4]);
        float4 s = make_float4(v1.x + v2.x, v1.y + v2.y, v1.z + v2.z, v1.w + v2.w);
        size_t off = (size_t)blockIdx.x * Nn * Dd + (size_t)(n0 + row) * Dd + 4 * q4;
        *reinterpret_cast<float4*>(&g_qpart[off]) = s;
    }
}

// ---------------------------------------------------------------------------
__global__ void k_update(float sigmat, int first, int last, float* __restrict__ out) {
    int i4 = blockIdx.x * blockDim.x + threadIdx.x;
    if (i4 >= Nn * Dd / 4) return;
    int n = i4 >> 4;

    float mx = -1e30f;
#pragma unroll
    for (int s = 0; s < MBLK; s++) mx = fmaxf(mx, g_pmax[s * Nn + n]);
    float rsum = 0.f;
    float4 q = make_float4(0.f, 0.f, 0.f, 0.f);
#pragma unroll
    for (int s = 0; s < MBLK; s++) {
        float ef = __expf(g_pmax[s * Nn + n] - mx);
        rsum = fmaf(g_psum[s * Nn + n], ef, rsum);
        float4 v = *reinterpret_cast<const float4*>(
            &g_qpart[(size_t)s * Nn * Dd + 4 * i4]);
        q.x = fmaf(v.x, ef, q.x);
        q.y = fmaf(v.y, ef, q.y);
        q.z = fmaf(v.z, ef, q.z);
        q.w = fmaf(v.w, ef, q.w);
    }
    float inv = 1.f / rsum;
    float4 xe = *reinterpret_cast<const float4*>(&g_xeff[4 * i4]);
    float4 xt = *reinterpret_cast<const float4*>(&g_xt[4 * i4]);
    float4 G1o = make_float4(0.f, 0.f, 0.f, 0.f);
    if (!first) G1o = *reinterpret_cast<const float4*>(&g_G1[4 * i4]);
    float4 G, xe2, xh, xl;
    float* Gp = &G.x; float* qp = &q.x; float* xep = &xe.x;
    float* xtp = &xt.x; float* xe2p = &xe2.x; float* xhp = &xh.x; float* xlp = &xl.x;
    float* G1p = &G1o.x;
#pragma unroll
    for (int e = 0; e < 4; e++) {
        float Gv = ((1.f - S0c) * xep[e] - qp[e] * inv) / sigmat;
        Gp[e] = Gv;
        if (!first) xtp[e] = xtp[e] - (G1p[e] + Gv) * (Hh * 0.5f);
        float x2 = xtp[e] - Hh * Gv;
        xe2p[e] = x2;
        u32 hb = to_tf32(x2);
        float hf = __uint_as_float(hb);
        xhp[e] = hf;
        xlp[e] = __uint_as_float(to_tf32(x2 - hf));
    }
    if (!first) *reinterpret_cast<float4*>(&g_xt[4 * i4]) = xt;
    *reinterpret_cast<float4*>(&g_G1[4 * i4]) = G;
    *reinterpret_cast<float4*>(&g_xeff[4 * i4]) = xe2;
    *reinterpret_cast<float4*>(&g_xh32[4 * i4]) = xh;
    *reinterpret_cast<float4*>(&g_xl32[4 * i4]) = xl;
    if (last) *reinterpret_cast<float4*>(&out[4 * i4]) = xt;
}

// ---------------------------------------------------------------------------
extern "C" void kernel_launch(void* const* d_in, const int* in_sizes, int n_in,
                              void* d_out, int out_size) {
    const float* z = (const float*)d_in[0];
    const float* x0 = (const float*)d_in[1];

    const int SMEM_F = 112640;
    cudaFuncSetAttribute(k_fused, cudaFuncAttributeMaxDynamicSharedMemorySize,
                         SMEM_F);

    k_init<<<(Nn * Dd + 255) / 256, 256>>>(z, x0);

    for (int e = 0; e < Tt; e++) {
        float t = (e == 0) ? 1.0f : (float)(Tt - e) / (float)Tt;
        float alphat = 1.0f - t;
        float sigmat = S0c + (1.0f - S0c) * t;
        float inv2s2 = 1.0f / (sigmat * sigmat);
        float scale = alphat * inv2s2;
        float c2 = 0.5f * alphat * alphat * inv2s2;

        k_fused<<<dim3(MBLK, 32), 256, SMEM_F>>>(scale, c2);
        k_update<<<(Nn * Dd / 4) / 256, 256>>>(sigmat, e == 0, e == Tt - 1,
                                               (float*)d_out);
    }
}